// round 17
// baseline (speedup 1.0000x reference)
#include <cuda_runtime.h>
#include <cuda_fp16.h>
#include <cstdint>

// GRUController via fp16 tensor cores (mma.sync m16n8k16, fp32 accum/epilogue).
// R16: encoder merges L0(t+1)+L1(t) into one phase (1 barrier/step, shared h0
// A-fragments). 512 threads = 2 independent halves x 8 n-tile warps.
// L1 B-frags in registers; L0 B-frags from smem (dual-accumulator reg budget).

typedef uint32_t u32;

#define TIN  512
#define TOUT 180
#define NT   512
#define HSW  40   // h row stride in 32-bit words

// 32-bit-word offsets in dynamic smem
#define OFF_BL0   0        // 96 frags * 64 words  (L0 B-frags, resident in smem)
#define OFF_BL1   6144     // 192 frags * 64 words (staging for L1 B-frags)
#define OFF_H0A   18432    // 64*40 words
#define OFF_H0B   20992
#define OFF_H1A   23552
#define OFF_H1B   26112
#define OFF_B0    28672    // 256 floats: bR,bZ,bI,bH
#define OFF_B1    28928
#define OFF_W0S   29184    // 384 floats: layer0 input weights [j][2]
#define OFF_XST   29568    // 2 slots * 64 rows * 2 floats
#define OFF_OUTW  29824    // 64
#define OFF_PART  29888    // 8 jg * 64 rows
#define SMEM_FLOATS 30400
#define SMEM_BYTES  (SMEM_FLOATS * 4)   // 121,600 B

__device__ __forceinline__ float tanh_t(float x) {
    float y; asm("tanh.approx.f32 %0,%1;" : "=f"(y) : "f"(x)); return y;
}
__device__ __forceinline__ float sigm_t(float x) {
    return fmaf(tanh_t(0.5f * x), 0.5f, 0.5f);
}
__device__ __forceinline__ u32 pack_h2(float lo, float hi) {
    __half2 h = __floats2half2_rn(lo, hi);
    return *(u32*)&h;
}
__device__ __forceinline__ float2 unpack_h2(u32 v) {
    return __half22float2(*(__half2*)&v);
}
__device__ __forceinline__ void mma16(float* c, u32 a0, u32 a1, u32 a2, u32 a3,
                                      u32 b0, u32 b1) {
    asm volatile(
        "mma.sync.aligned.m16n8k16.row.col.f32.f16.f16.f32 "
        "{%0,%1,%2,%3},{%4,%5,%6,%7},{%8,%9},{%0,%1,%2,%3};"
        : "+f"(c[0]), "+f"(c[1]), "+f"(c[2]), "+f"(c[3])
        : "r"(a0), "r"(a1), "r"(a2), "r"(a3), "r"(b0), "r"(b1));
}

// B-frag staging (fp16) into smem: frag n8 x k16. lane l: word0 = W[n][k0..k0+1],
// word1 = W[n][k0+8..k0+9], n = base + (l>>2), k0 = chunk*16 + (l&3)*2.
__device__ void load_weights_tc(float* __restrict__ sm,
                                const float* __restrict__ Wih0, int nin,
                                const float* __restrict__ Whh0,
                                const float* __restrict__ bih0, const float* __restrict__ bhh0,
                                const float* __restrict__ Wih1, const float* __restrict__ Whh1,
                                const float* __restrict__ bih1, const float* __restrict__ bhh1,
                                int tid) {
    u32* smw = (u32*)sm;
    for (int i = tid; i < 96 * 32; i += NT) {
        int f = i >> 5, l = i & 31;
        int gate = f >> 5, rem = f & 31, nt = rem >> 2, ch = rem & 3;
        int row = gate * 64 + nt * 8 + (l >> 2);
        int k0 = ch * 16 + (l & 3) * 2;
        smw[OFF_BL0 + f * 64 + l * 2]     = pack_h2(Whh0[row * 64 + k0],     Whh0[row * 64 + k0 + 1]);
        smw[OFF_BL0 + f * 64 + l * 2 + 1] = pack_h2(Whh0[row * 64 + k0 + 8], Whh0[row * 64 + k0 + 9]);
    }
    for (int i = tid; i < 192 * 32; i += NT) {
        int f = i >> 5, l = i & 31;
        int gate = f >> 6, rem = f & 63, nt = rem >> 3, ch = rem & 7;
        int row = gate * 64 + nt * 8 + (l >> 2);
        int k0 = (ch & 3) * 16 + (l & 3) * 2;
        const float* src = (ch < 4) ? Wih1 : Whh1;
        smw[OFF_BL1 + f * 64 + l * 2]     = pack_h2(src[row * 64 + k0],     src[row * 64 + k0 + 1]);
        smw[OFF_BL1 + f * 64 + l * 2 + 1] = pack_h2(src[row * 64 + k0 + 8], src[row * 64 + k0 + 9]);
    }
    for (int j = tid; j < 192; j += NT) {
        sm[OFF_W0S + j * 2]     = Wih0[j * nin];
        sm[OFF_W0S + j * 2 + 1] = (nin == 2) ? Wih0[j * 2 + 1] : 0.0f;
    }
    if (tid < 64) {
        sm[OFF_B0 + tid]       = bih0[tid]       + bhh0[tid];
        sm[OFF_B0 + 64 + tid]  = bih0[64 + tid]  + bhh0[64 + tid];
        sm[OFF_B0 + 128 + tid] = bih0[128 + tid];
        sm[OFF_B0 + 192 + tid] = bhh0[128 + tid];
        sm[OFF_B1 + tid]       = bih1[tid]       + bhh1[tid];
        sm[OFF_B1 + 64 + tid]  = bih1[64 + tid]  + bhh1[64 + tid];
        sm[OFF_B1 + 128 + tid] = bih1[128 + tid];
        sm[OFF_B1 + 192 + tid] = bhh1[128 + tid];
    }
}

extern "C" __global__ void __launch_bounds__(NT, 1)
gru_controller_kernel(const float* __restrict__ x,
                      const float* eWih0, const float* eWhh0, const float* ebih0, const float* ebhh0,
                      const float* eWih1, const float* eWhh1, const float* ebih1, const float* ebhh1,
                      const float* dWih0, const float* dWhh0, const float* dbih0, const float* dbhh0,
                      const float* dWih1, const float* dWhh1, const float* dbih1, const float* dbhh1,
                      const float* __restrict__ outW, const float* __restrict__ outb,
                      float* __restrict__ out) {
    extern __shared__ float sm[];
    u32* smw = (u32*)sm;
    const int tid = threadIdx.x;
    const int w = tid >> 5, l = tid & 31;
    const int mg = w >> 3, jg = w & 7;      // half mg (rows mg*32..+31), n-tile jg
    const int g = l >> 2, tq = l & 3;
    const int rb0 = mg * 32;
    const int rbase = blockIdx.x * 64;
    const int lt = tid & 255;               // thread id within half

    auto barh = [&]() {
        asm volatile("bar.sync %0, 256;" :: "r"(1 + mg) : "memory");
    };

    // dual accumulator sets: a0* = layer0, a1* = layer1   [mt][q]
    float a0R[2][4], a0Z[2][4], a0I[2][4], a0H[2][4];
    float a1R[2][4], a1Z[2][4], a1I[2][4], a1H[2][4];
    uint2 bl1[3][8];   // L1 B-frags in registers

    auto load_b_regs = [&]() {
#pragma unroll
        for (int gate = 0; gate < 3; gate++)
#pragma unroll
            for (int ch = 0; ch < 8; ch++)
                bl1[gate][ch] =
                    *(const uint2*)&smw[OFF_BL1 + (gate * 64 + jg * 8 + ch) * 64 + l * 2];
    };

    // init L0 accums: bias + x @ Wih0^T (reads x slot)
    auto init0 = [&](int slot) {
        const int col0 = jg * 8 + 2 * tq;
        float2 bR = *(const float2*)&sm[OFF_B0 + col0];
        float2 bZ = *(const float2*)&sm[OFF_B0 + 64 + col0];
        float2 bI = *(const float2*)&sm[OFF_B0 + 128 + col0];
        float2 bH = *(const float2*)&sm[OFF_B0 + 192 + col0];
        float2 wr0 = *(const float2*)&sm[OFF_W0S + col0 * 2];
        float2 wr1 = *(const float2*)&sm[OFF_W0S + (col0 + 1) * 2];
        float2 wz0 = *(const float2*)&sm[OFF_W0S + (64 + col0) * 2];
        float2 wz1 = *(const float2*)&sm[OFF_W0S + (64 + col0 + 1) * 2];
        float2 wn0 = *(const float2*)&sm[OFF_W0S + (128 + col0) * 2];
        float2 wn1 = *(const float2*)&sm[OFF_W0S + (128 + col0 + 1) * 2];
#pragma unroll
        for (int mt = 0; mt < 2; mt++) {
            float2 xlo = *(const float2*)&sm[OFF_XST + slot * 128 + (rb0 + mt * 16 + g) * 2];
            float2 xhi = *(const float2*)&sm[OFF_XST + slot * 128 + (rb0 + mt * 16 + g + 8) * 2];
#pragma unroll
            for (int h = 0; h < 2; h++) {
                float x0 = h ? xhi.x : xlo.x;
                float x1 = h ? xhi.y : xlo.y;
                a0R[mt][2 * h]     = bR.x + x0 * wr0.x + x1 * wr0.y;
                a0R[mt][2 * h + 1] = bR.y + x0 * wr1.x + x1 * wr1.y;
                a0Z[mt][2 * h]     = bZ.x + x0 * wz0.x + x1 * wz0.y;
                a0Z[mt][2 * h + 1] = bZ.y + x0 * wz1.x + x1 * wz1.y;
                a0I[mt][2 * h]     = bI.x + x0 * wn0.x + x1 * wn0.y;
                a0I[mt][2 * h + 1] = bI.y + x0 * wn1.x + x1 * wn1.y;
                a0H[mt][2 * h]     = bH.x;
                a0H[mt][2 * h + 1] = bH.y;
            }
        }
    };

    // init L1 accums: bias only
    auto init1 = [&]() {
        const int col0 = jg * 8 + 2 * tq;
        float2 bR = *(const float2*)&sm[OFF_B1 + col0];
        float2 bZ = *(const float2*)&sm[OFF_B1 + 64 + col0];
        float2 bI = *(const float2*)&sm[OFF_B1 + 128 + col0];
        float2 bH = *(const float2*)&sm[OFF_B1 + 192 + col0];
#pragma unroll
        for (int mt = 0; mt < 2; mt++) {
            a1R[mt][0] = bR.x; a1R[mt][1] = bR.y; a1R[mt][2] = bR.x; a1R[mt][3] = bR.y;
            a1Z[mt][0] = bZ.x; a1Z[mt][1] = bZ.y; a1Z[mt][2] = bZ.x; a1Z[mt][3] = bZ.y;
            a1I[mt][0] = bI.x; a1I[mt][1] = bI.y; a1I[mt][2] = bI.x; a1I[mt][3] = bI.y;
            a1H[mt][0] = bH.x; a1H[mt][1] = bH.y; a1H[mt][2] = bH.x; a1H[mt][3] = bH.y;
        }
    };

    // load one A-frag set for chunk ch from buffer hs
    auto load_a = [&](const u32* hs, int ch, u32 (&a)[2][4]) {
        int kw = (ch & 3) * 8 + tq * 2;
#pragma unroll
        for (int mt = 0; mt < 2; mt++) {
            int rlo = rb0 + mt * 16 + g;
            uint2 lo = *(const uint2*)&hs[rlo * HSW + kw];
            uint2 hi = *(const uint2*)&hs[(rlo + 8) * HSW + kw];
            a[mt][0] = lo.x; a[mt][1] = hi.x; a[mt][2] = lo.y; a[mt][3] = hi.y;
        }
    };

    // L0-only contraction (decoder path); B-frags from smem
    auto mma_l0 = [&](const u32* hs) {
#pragma unroll
        for (int ch = 0; ch < 4; ch++) {
            u32 a[2][4];
            load_a(hs, ch, a);
            uint2 bR = *(const uint2*)&smw[OFF_BL0 + (0 * 32 + jg * 4 + ch) * 64 + l * 2];
            uint2 bZ = *(const uint2*)&smw[OFF_BL0 + (1 * 32 + jg * 4 + ch) * 64 + l * 2];
            uint2 bN = *(const uint2*)&smw[OFF_BL0 + (2 * 32 + jg * 4 + ch) * 64 + l * 2];
#pragma unroll
            for (int mt = 0; mt < 2; mt++) {
                mma16(a0R[mt], a[mt][0], a[mt][1], a[mt][2], a[mt][3], bR.x, bR.y);
                mma16(a0Z[mt], a[mt][0], a[mt][1], a[mt][2], a[mt][3], bZ.x, bZ.y);
                mma16(a0H[mt], a[mt][0], a[mt][1], a[mt][2], a[mt][3], bN.x, bN.y);
            }
        }
    };

    // L1-only contraction (decoder path)
    auto mma_l1 = [&](const u32* h0, const u32* h1) {
#pragma unroll
        for (int ch = 0; ch < 8; ch++) {
            const u32* hs = (ch < 4) ? h0 : h1;
            u32 a[2][4];
            load_a(hs, ch, a);
#pragma unroll
            for (int mt = 0; mt < 2; mt++) {
                mma16(a1R[mt], a[mt][0], a[mt][1], a[mt][2], a[mt][3], bl1[0][ch].x, bl1[0][ch].y);
                mma16(a1Z[mt], a[mt][0], a[mt][1], a[mt][2], a[mt][3], bl1[1][ch].x, bl1[1][ch].y);
                if (ch < 4)
                    mma16(a1I[mt], a[mt][0], a[mt][1], a[mt][2], a[mt][3], bl1[2][ch].x, bl1[2][ch].y);
                else
                    mma16(a1H[mt], a[mt][0], a[mt][1], a[mt][2], a[mt][3], bl1[2][ch].x, bl1[2][ch].y);
            }
        }
    };

    // merged contraction: h0 chunks feed L0 (all gates) and L1-ih; h1 chunks feed L1-hh
    auto mma_merged = [&](const u32* h0s, const u32* h1s, bool doL0, bool doL1) {
#pragma unroll
        for (int ch = 0; ch < 4; ch++) {
            u32 a[2][4];
            load_a(h0s, ch, a);
            if (doL0) {
                uint2 bR = *(const uint2*)&smw[OFF_BL0 + (0 * 32 + jg * 4 + ch) * 64 + l * 2];
                uint2 bZ = *(const uint2*)&smw[OFF_BL0 + (1 * 32 + jg * 4 + ch) * 64 + l * 2];
                uint2 bN = *(const uint2*)&smw[OFF_BL0 + (2 * 32 + jg * 4 + ch) * 64 + l * 2];
#pragma unroll
                for (int mt = 0; mt < 2; mt++) {
                    mma16(a0R[mt], a[mt][0], a[mt][1], a[mt][2], a[mt][3], bR.x, bR.y);
                    mma16(a0Z[mt], a[mt][0], a[mt][1], a[mt][2], a[mt][3], bZ.x, bZ.y);
                    mma16(a0H[mt], a[mt][0], a[mt][1], a[mt][2], a[mt][3], bN.x, bN.y);
                }
            }
            if (doL1) {
#pragma unroll
                for (int mt = 0; mt < 2; mt++) {
                    mma16(a1R[mt], a[mt][0], a[mt][1], a[mt][2], a[mt][3], bl1[0][ch].x, bl1[0][ch].y);
                    mma16(a1Z[mt], a[mt][0], a[mt][1], a[mt][2], a[mt][3], bl1[1][ch].x, bl1[1][ch].y);
                    mma16(a1I[mt], a[mt][0], a[mt][1], a[mt][2], a[mt][3], bl1[2][ch].x, bl1[2][ch].y);
                }
            }
        }
        if (doL1) {
#pragma unroll
            for (int ch = 4; ch < 8; ch++) {
                u32 a[2][4];
                load_a(h1s, ch, a);
#pragma unroll
                for (int mt = 0; mt < 2; mt++) {
                    mma16(a1R[mt], a[mt][0], a[mt][1], a[mt][2], a[mt][3], bl1[0][ch].x, bl1[0][ch].y);
                    mma16(a1Z[mt], a[mt][0], a[mt][1], a[mt][2], a[mt][3], bl1[1][ch].x, bl1[1][ch].y);
                    mma16(a1H[mt], a[mt][0], a[mt][1], a[mt][2], a[mt][3], bl1[2][ch].x, bl1[2][ch].y);
                }
            }
        }
    };

    // fp32 epilogue; h word for n-tile jg at 2tq: word 8(jg>>1)+2tq+(jg&1)
    auto update = [&](const u32* hs, u32* hd, bool head,
                      float (&aR)[2][4], float (&aZ)[2][4],
                      float (&aI)[2][4], float (&aH)[2][4]) {
        const int wq = 8 * (jg >> 1) + 2 * tq + (jg & 1);
        float pr[2][2] = {{0.0f, 0.0f}, {0.0f, 0.0f}};
        float2 wo = head ? *(const float2*)&sm[OFF_OUTW + jg * 8 + 2 * tq]
                         : make_float2(0.f, 0.f);
#pragma unroll
        for (int mt = 0; mt < 2; mt++) {
            int rlo = rb0 + mt * 16 + g, rhi = rlo + 8;
            float2 hlo = unpack_h2(hs[rlo * HSW + wq]);
            float2 hhi = unpack_h2(hs[rhi * HSW + wq]);
            const float hold[4] = {hlo.x, hlo.y, hhi.x, hhi.y};
            float o[4];
#pragma unroll
            for (int q = 0; q < 4; q++) {
                float r = sigm_t(aR[mt][q]);
                float z = sigm_t(aZ[mt][q]);
                float n = tanh_t(fmaf(r, aH[mt][q], aI[mt][q]));
                o[q] = fmaf(z, hold[q] - n, n);
            }
            hd[rlo * HSW + wq] = pack_h2(o[0], o[1]);
            hd[rhi * HSW + wq] = pack_h2(o[2], o[3]);
            if (head) {
                pr[mt][0] = fmaf(o[0], wo.x, fmaf(o[1], wo.y, pr[mt][0]));
                pr[mt][1] = fmaf(o[2], wo.x, fmaf(o[3], wo.y, pr[mt][1]));
            }
        }
        if (head) {
#pragma unroll
            for (int mt = 0; mt < 2; mt++)
#pragma unroll
                for (int h = 0; h < 2; h++) {
                    float v = pr[mt][h];
                    v += __shfl_xor_sync(0xffffffffu, v, 1);
                    v += __shfl_xor_sync(0xffffffffu, v, 2);
                    if (tq == 0)
                        sm[OFF_PART + jg * 64 + rb0 + mt * 16 + h * 8 + g] = v;
                }
        }
    };

    // stage x(t) for this half's 32 rows into slot
    auto stage_x = [&](int t, int slot) {
        if (lt < 64) {
            int r = rb0 + (lt >> 1), ch = lt & 1;
            sm[OFF_XST + slot * 128 + r * 2 + ch] = x[((long)(rbase + r) * TIN + t) * 2 + ch];
        }
    };

    // ---------------- setup ----------------
    for (int i = tid; i < 4 * 64 * HSW; i += NT) smw[OFF_H0A + i] = 0u;
    load_weights_tc(sm, eWih0, 2, eWhh0, ebih0, ebhh0, eWih1, eWhh1, ebih1, ebhh1, tid);
    if (tid < 64) sm[OFF_OUTW + tid] = outW[tid];
    __syncthreads();
    load_b_regs();
    stage_x(0, 0);
    barh();

    // ========== encoder: merged phases, it = 0..TIN ==========
    // phase(it): L0(it) [reads h0(it-1), x(it)]  +  L1(it-1) [reads h0(it-1), h1(it-2)]
    for (int it = 0; it <= TIN; it++) {
        const int p = it & 1;
        const bool doL0 = (it < TIN);
        const bool doL1 = (it >= 1);
        const u32* h0s = smw + (p ? OFF_H0B : OFF_H0A);
        u32*       h0d = smw + (p ? OFF_H0A : OFF_H0B);
        const u32* h1s = smw + (p ? OFF_H1B : OFF_H1A);
        u32*       h1d = smw + (p ? OFF_H1A : OFF_H1B);

        if (it + 1 < TIN) stage_x(it + 1, (it + 1) & 1);

        if (doL0) init0(it & 1);
        if (doL1) init1();
        mma_merged(h0s, h1s, doL0, doL1);
        if (doL0) update(h0s, h0d, false, a0R, a0Z, a0I, a0H);
        if (doL1) update(h1s, h1d, false, a1R, a1Z, a1I, a1H);
        barh();
    }
    // final states: h0(TIN-1) in H0A (written at it=TIN-1, p=1),
    //               h1(TIN-1) in H1B (written at it=TIN,   p=0)

    // ========== swap to decoder weights ==========
    __syncthreads();
    load_weights_tc(sm, dWih0, 1, dWhh0, dbih0, dbhh0, dWih1, dWhh1, dbih1, dbhh1, tid);
    if (tid < 64) {
        sm[OFF_XST + tid * 2]     = 0.0f;   // prev = 0 (channel 1 stays 0)
        sm[OFF_XST + tid * 2 + 1] = 0.0f;
    }
    __syncthreads();
    load_b_regs();
    const float ob = outb[0];

    // ========== decoder (per-half, R15 two-phase structure) ==========
    int ph0 = 0, ph1 = 1;   // h0 final in H0A, h1 final in H1B
    for (int t = 0; t < TOUT; t++) {
        const u32* h0s = smw + (ph0 ? OFF_H0B : OFF_H0A);
        u32*       h0d = smw + (ph0 ? OFF_H0A : OFF_H0B);
        const u32* h1s = smw + (ph1 ? OFF_H1B : OFF_H1A);
        u32*       h1d = smw + (ph1 ? OFF_H1A : OFF_H1B);

        init0(0);   // prev in slot 0
        mma_l0(h0s);
        update(h0s, h0d, false, a0R, a0Z, a0I, a0H);
        barh();

        init1();
        mma_l1(h0d, h1s);
        update(h1s, h1d, true, a1R, a1Z, a1I, a1H);
        barh();

        if (lt < 32) {
            int r = rb0 + lt;
            float acc = ob;
#pragma unroll
            for (int c = 0; c < 8; c++) acc += sm[OFF_PART + c * 64 + r];
            sm[OFF_XST + r * 2] = acc;     // prev for next step
            out[(long)(rbase + r) * TOUT + t] = acc;
        }
        barh();
        ph0 ^= 1; ph1 ^= 1;
    }
}

extern "C" void kernel_launch(void* const* d_in, const int* in_sizes, int n_in,
                              void* d_out, int out_size) {
    const float* x     = (const float*)d_in[0];
    const float* eWih0 = (const float*)d_in[1];
    const float* eWhh0 = (const float*)d_in[2];
    const float* ebih0 = (const float*)d_in[3];
    const float* ebhh0 = (const float*)d_in[4];
    const float* eWih1 = (const float*)d_in[5];
    const float* eWhh1 = (const float*)d_in[6];
    const float* ebih1 = (const float*)d_in[7];
    const float* ebhh1 = (const float*)d_in[8];
    const float* dWih0 = (const float*)d_in[9];
    const float* dWhh0 = (const float*)d_in[10];
    const float* dbih0 = (const float*)d_in[11];
    const float* dbhh0 = (const float*)d_in[12];
    const float* dWih1 = (const float*)d_in[13];
    const float* dWhh1 = (const float*)d_in[14];
    const float* dbih1 = (const float*)d_in[15];
    const float* dbhh1 = (const float*)d_in[16];
    const float* outW  = (const float*)d_in[17];
    const float* outb  = (const float*)d_in[18];
    float* out = (float*)d_out;

    cudaFuncSetAttribute(gru_controller_kernel,
                         cudaFuncAttributeMaxDynamicSharedMemorySize, SMEM_BYTES);
    gru_controller_kernel<<<128, NT, SMEM_BYTES>>>(
        x, eWih0, eWhh0, ebih0, ebhh0, eWih1, eWhh1, ebih1, ebhh1,
        dWih0, dWhh0, dbih0, dbhh0, dWih1, dWhh1, dbih1, dbhh1,
        outW, outb, out);
}